// round 16
// baseline (speedup 1.0000x reference)
#include <cuda_runtime.h>
#include <math.h>
#include <stdint.h>

// Problem constants (fixed by setup_inputs)
#define HH 512
#define WW 512
#define HW (HH * WW)            // 262144
#define VV 64
#define V3 (VV * VV * VV)       // 262144
#define NB 32
#define NPIX (NB * HW)          // 8388608

// Reachability: d>0 && in-range forces cz = rint((d+2)*15.75) in [32,63].
// Scratch: [b][((cx*64+cy)*32 + (cz-32))] float4{count,r,g,b}; 64 MB.
//
// NO zero kernel: finalize rezeros every scratch line it reads (L2-hit
// stores riding under its DRAM output writes). Scratch is zero at every
// call boundary (load-time init covers call 1; finalize's rezero covers
// all replays). Eviction-safe: a dirty line (partials or zeros) written
// back to DRAM is refetched with its correct value - no discard, no L2
// retention assumption.
#define SCR_PER_B (VV * VV * 32)     // 131072 (= 1<<17) entries per batch
#define NSCRATCH (NB * SCR_PER_B)    // 4194304 entries = 64 MB

__device__ __align__(128) float4 g_acc[NSCRATCH];

// ---- helpers ---------------------------------------------------------------
__device__ __forceinline__ uint64_t pol_evict_first() {
    uint64_t p;
    asm("createpolicy.fractional.L2::evict_first.b64 %0, 1.0;" : "=l"(p));
    return p;
}
__device__ __forceinline__ float4 ldg_stream(const float* a, uint64_t pol) {
    float4 v;
    asm("ld.global.nc.L2::cache_hint.v4.f32 {%0,%1,%2,%3}, [%4], %5;"
        : "=f"(v.x), "=f"(v.y), "=f"(v.z), "=f"(v.w) : "l"(a), "l"(pol));
    return v;
}
__device__ __forceinline__ void ldg256(const float* p, float4& v0, float4& v1) {
    asm volatile("ld.global.v8.f32 {%0,%1,%2,%3,%4,%5,%6,%7}, [%8];"
                 : "=f"(v0.x), "=f"(v0.y), "=f"(v0.z), "=f"(v0.w),
                   "=f"(v1.x), "=f"(v1.y), "=f"(v1.z), "=f"(v1.w)
                 : "l"(p));
}
__device__ __forceinline__ void stg256(float* p, float4 v0, float4 v1) {
    asm volatile("st.global.v8.f32 [%0], {%1,%2,%3,%4,%5,%6,%7,%8};"
                 :: "l"(p), "f"(v0.x), "f"(v0.y), "f"(v0.z), "f"(v0.w),
                    "f"(v1.x), "f"(v1.y), "f"(v1.z), "f"(v1.w)
                 : "memory");
}
__device__ __forceinline__ void stg256_hint(float* p, float4 v0, float4 v1,
                                            uint64_t pol) {
    asm volatile("st.global.L2::cache_hint.v8.f32 [%0], "
                 "{%1,%2,%3,%4,%5,%6,%7,%8}, %9;"
                 :: "l"(p), "f"(v0.x), "f"(v0.y), "f"(v0.z), "f"(v0.w),
                    "f"(v1.x), "f"(v1.y), "f"(v1.z), "f"(v1.w), "l"(pol)
                 : "memory");
}

// --------------------------------------------------------------- splat ----
__global__ __launch_bounds__(256) void splat_kernel(const float* __restrict__ rgbd) {
    int t = blockIdx.x * blockDim.x + threadIdx.x;
    if (t >= NPIX / 4) return;
    uint64_t pfirst = pol_evict_first();

    int idx = t << 2;                // first of 4 consecutive pixels
    int b = idx >> 18;               // / HW
    int p = idx & (HW - 1);          // % HW   (multiple of 4)
    int h = p >> 9;
    int w0 = p & (WW - 1);

    const float* base = rgbd + (size_t)b * (4 * HW);
    float4 d4 = ldg_stream(base + 3 * HW + p, pfirst);

    float dv[4] = {d4.x, d4.y, d4.z, d4.w};
    int   lin[4];
    bool  valid[4];
    bool  any = false;
    float yb = (float)h - 256.0f;    // fx=fy=256, cx=cy=256

    #pragma unroll
    for (int k = 0; k < 4; k++) {
        float d = dv[k];
        bool ok = (d > 0.0f) && (d < 10.0f) && isfinite(d);
        float x = ((float)(w0 + k) - 256.0f) * d * (1.0f / 256.0f);
        float y = yb * d * (1.0f / 256.0f);
        // rintf = round-half-even = jnp.round; 15.75 == 63/4 exactly, same
        // single rounding as ((p+2)/4)*63 in the reference.
        float fx_ = rintf((x + 2.0f) * 15.75f);
        float fy_ = rintf((y + 2.0f) * 15.75f);
        float fz_ = rintf((d + 2.0f) * 15.75f);
        ok = ok && (fx_ >= 0.0f) && (fx_ <= 63.0f)
                && (fy_ >= 0.0f) && (fy_ <= 63.0f)
                && (fz_ >= 32.0f) && (fz_ <= 63.0f);
        valid[k] = ok;
        any = any || ok;
        int cx = (int)fx_, cy = (int)fy_, cz = (int)fz_;
        lin[k] = (b << 17) + ((((cx << 6) | cy) << 5) | (cz - 32));
    }

    if (!any) return;

    float4 r4 = ldg_stream(base + 0 * HW + p, pfirst);
    float4 g4 = ldg_stream(base + 1 * HW + p, pfirst);
    float4 b4 = ldg_stream(base + 2 * HW + p, pfirst);
    float rv[4] = {r4.x, r4.y, r4.z, r4.w};
    float gv[4] = {g4.x, g4.y, g4.z, g4.w};
    float bv[4] = {b4.x, b4.y, b4.z, b4.w};

    #pragma unroll
    for (int k = 0; k < 4; k++) {
        if (valid[k]) {
            float* a = (float*)&g_acc[lin[k]];
            asm volatile("red.global.add.v4.f32 [%0], {%1,%2,%3,%4};"
                         :: "l"(a), "f"(1.0f), "f"(rv[k]), "f"(gv[k]),
                            "f"(bv[k]) : "memory");
        }
    }
}

// ------------------------------------------------------------ finalize ----
// Branch-free resolve: count==0 => sums exactly 0 => sum*rcp(max(count,1))==0.
__device__ __forceinline__ void resolve(float4 a, float& occ, float& r,
                                        float& g, float& b) {
    float inv;
    asm("rcp.approx.f32 %0, %1;" : "=f"(inv) : "f"(fmaxf(a.x, 1.0f)));
    occ = (a.x > 0.0f) ? 1.0f : 0.0f;
    r = a.y * inv;
    g = a.z * inv;
    b = a.w * inv;
}

// Thread t owns ONE 128B scratch line (8 entries): 4 x LDG.256 in, 4 x
// STG.256 REZERO of the same line (L2-hit stores; keeps the zero invariant
// for the next call), then 8 x STG.256 of output (occupied + zero halves,
// evict_first -> drains to DRAM).
__global__ __launch_bounds__(256) void finalize_kernel(float* __restrict__ out) {
    int t = blockIdx.x * blockDim.x + threadIdx.x;
    if (t >= NSCRATCH / 8) return;
    uint64_t pfirst = pol_evict_first();

    int s = t << 3;                    // 8 contiguous entries (one 128B line)
    int b = s >> 17;                   // batch
    int sl = s & (SCR_PER_B - 1);      // ((cx*64+cy)*32 + (cz-32)), mult of 8

    float* sp = (float*)&g_acc[s];
    float4 a[8];
    ldg256(sp,      a[0], a[1]);
    ldg256(sp + 8,  a[2], a[3]);
    ldg256(sp + 16, a[4], a[5]);
    ldg256(sp + 24, a[6], a[7]);

    // Rezero the line (values already in registers). L2-hit stores; these
    // replace both the discard and the standalone zero kernel.
    float4 z = make_float4(0.f, 0.f, 0.f, 0.f);
    stg256(sp,      z, z);
    stg256(sp + 8,  z, z);
    stg256(sp + 16, z, z);
    stg256(sp + 24, z, z);

    float4 occ0, rr0, gg0, bb0, occ1, rr1, gg1, bb1;
    resolve(a[0], occ0.x, rr0.x, gg0.x, bb0.x);
    resolve(a[1], occ0.y, rr0.y, gg0.y, bb0.y);
    resolve(a[2], occ0.z, rr0.z, gg0.z, bb0.z);
    resolve(a[3], occ0.w, rr0.w, gg0.w, bb0.w);
    resolve(a[4], occ1.x, rr1.x, gg1.x, bb1.x);
    resolve(a[5], occ1.y, rr1.y, gg1.y, bb1.y);
    resolve(a[6], occ1.z, rr1.z, gg1.z, bb1.z);
    resolve(a[7], occ1.w, rr1.w, gg1.w, bb1.w);

    int rhi = (sl >> 5) << 6;          // (cx*64+cy)*64
    int rocc = rhi + (sl & 31) + 32;   // occupied half (32B aligned)
    int rzer = rhi + (sl & 31);        // zero half (32B aligned)
    float* ob = out + (size_t)b * (4 * V3);

    stg256_hint(ob + rocc,          occ0, occ1, pfirst);
    stg256_hint(ob + V3 + rocc,     rr0,  rr1,  pfirst);
    stg256_hint(ob + 2 * V3 + rocc, gg0,  gg1,  pfirst);
    stg256_hint(ob + 3 * V3 + rocc, bb0,  bb1,  pfirst);

    stg256_hint(ob + rzer,          z, z, pfirst);
    stg256_hint(ob + V3 + rzer,     z, z, pfirst);
    stg256_hint(ob + 2 * V3 + rzer, z, z, pfirst);
    stg256_hint(ob + 3 * V3 + rzer, z, z, pfirst);
}

extern "C" void kernel_launch(void* const* d_in, const int* in_sizes, int n_in,
                              void* d_out, int out_size) {
    const float* rgbd = (const float*)d_in[0];
    float* out = (float*)d_out;

    const int T = 256;
    splat_kernel<<<(NPIX / 4) / T, T>>>(rgbd);
    finalize_kernel<<<(NSCRATCH / 8) / T, T>>>(out);
}

// round 17
// speedup vs baseline: 1.5870x; 1.5870x over previous
#include <cuda_runtime.h>
#include <math.h>
#include <stdint.h>

// Problem constants (fixed by setup_inputs)
#define HH 512
#define WW 512
#define HW (HH * WW)            // 262144
#define VV 64
#define V3 (VV * VV * VV)       // 262144
#define NB 32
#define NPIX (NB * HW)          // 8388608

// Reachability: d>0 && in-range forces cz = rint((d+2)*15.75) in [32,63].
// FRUSTUM: |x| <= d (|u-cx|<=fx) pins (cx,cy) to a square that grows with
// cz. With 2-voxel fp32 safety margin:
//   reachable  =>  cz >= max(cx-3, 60-cx, cy-3, 60-cy, 32)
// Only ~46% of the scratch is reachable; the rest stays DRAM-zero forever.
//
// Scratch: [b][((cx*64+cy)*32 + (cz-32))] float4{count,r,g,b}; 64 MB.
// Lifecycle: zero_frustum (dirty L2 fill of reachable tail only) -> splat
// REDs (L2) -> finalize reads + DISCARDs (no writeback) -> scratch's DRAM
// backing stays zero forever. Eviction-safe: zero_frustum re-heals every
// reachable line each call.
#define SCR_PER_B (VV * VV * 32)     // 131072 (= 1<<17) entries per batch
#define NSCRATCH (NB * SCR_PER_B)    // 4194304 entries = 64 MB
#define NROWS (NB * VV * VV)         // 131072 rows of 32 entries (512B)

__device__ __align__(128) float4 g_acc[NSCRATCH];

// mz(cx,cy): first reachable czrel (=cz-32) for this (cx,cy) row, with
// 2-voxel margin. Entries czrel < mz are provably never splatted.
__device__ __forceinline__ int row_mz(int cx, int cy) {
    int gx = max(cx - 3, 60 - cx);
    int gy = max(cy - 3, 60 - cy);
    int m = max(32, max(gx, gy));
    return m - 32;                   // 0..28
}

// ---- helpers ---------------------------------------------------------------
__device__ __forceinline__ uint64_t pol_evict_first() {
    uint64_t p;
    asm("createpolicy.fractional.L2::evict_first.b64 %0, 1.0;" : "=l"(p));
    return p;
}
__device__ __forceinline__ float4 ldg_stream(const float* a, uint64_t pol) {
    float4 v;
    asm("ld.global.nc.L2::cache_hint.v4.f32 {%0,%1,%2,%3}, [%4], %5;"
        : "=f"(v.x), "=f"(v.y), "=f"(v.z), "=f"(v.w) : "l"(a), "l"(pol));
    return v;
}
__device__ __forceinline__ void ldg256(const float* p, float4& v0, float4& v1) {
    asm volatile("ld.global.v8.f32 {%0,%1,%2,%3,%4,%5,%6,%7}, [%8];"
                 : "=f"(v0.x), "=f"(v0.y), "=f"(v0.z), "=f"(v0.w),
                   "=f"(v1.x), "=f"(v1.y), "=f"(v1.z), "=f"(v1.w)
                 : "l"(p));
}
__device__ __forceinline__ void stg256(float* p, float4 v0, float4 v1) {
    asm volatile("st.global.v8.f32 [%0], {%1,%2,%3,%4,%5,%6,%7,%8};"
                 :: "l"(p), "f"(v0.x), "f"(v0.y), "f"(v0.z), "f"(v0.w),
                    "f"(v1.x), "f"(v1.y), "f"(v1.z), "f"(v1.w)
                 : "memory");
}
__device__ __forceinline__ void stg256_hint(float* p, float4 v0, float4 v1,
                                            uint64_t pol) {
    asm volatile("st.global.L2::cache_hint.v8.f32 [%0], "
                 "{%1,%2,%3,%4,%5,%6,%7,%8}, %9;"
                 :: "l"(p), "f"(v0.x), "f"(v0.y), "f"(v0.z), "f"(v0.w),
                    "f"(v1.x), "f"(v1.y), "f"(v1.z), "f"(v1.w), "l"(pol)
                 : "memory");
}

// ------------------------------------------------ zero frustum scratch ----
// Warp per row batch: lane = czrel entry within the 512B row; only lanes
// >= mz store (coalesced predicated STG.128). ~29.5 MB instead of 64 MB.
__global__ __launch_bounds__(256) void zero_frustum_kernel() {
    int w = (blockIdx.x * 256 + threadIdx.x) >> 5;   // global warp id
    int lane = threadIdx.x & 31;
    float4 z = make_float4(0.f, 0.f, 0.f, 0.f);
    int row0 = w << 4;                               // 16 rows per warp
    #pragma unroll 4
    for (int i = 0; i < 16; i++) {
        int row = row0 + i;                          // [b][cx][cy]
        int cx = (row >> 6) & 63;
        int cy = row & 63;
        int mz = row_mz(cx, cy);
        if (lane >= mz) g_acc[(row << 5) + lane] = z;
    }
}

// --------------------------------------------------------------- splat ----
__global__ __launch_bounds__(256) void splat_kernel(const float* __restrict__ rgbd) {
    int t = blockIdx.x * blockDim.x + threadIdx.x;
    if (t >= NPIX / 4) return;
    uint64_t pfirst = pol_evict_first();

    int idx = t << 2;                // first of 4 consecutive pixels
    int b = idx >> 18;               // / HW
    int p = idx & (HW - 1);          // % HW   (multiple of 4)
    int h = p >> 9;
    int w0 = p & (WW - 1);

    const float* base = rgbd + (size_t)b * (4 * HW);
    float4 d4 = ldg_stream(base + 3 * HW + p, pfirst);

    float dv[4] = {d4.x, d4.y, d4.z, d4.w};
    int   lin[4];
    bool  valid[4];
    bool  any = false;
    float yb = (float)h - 256.0f;    // fx=fy=256, cx=cy=256

    #pragma unroll
    for (int k = 0; k < 4; k++) {
        float d = dv[k];
        bool ok = (d > 0.0f) && (d < 10.0f) && isfinite(d);
        float x = ((float)(w0 + k) - 256.0f) * d * (1.0f / 256.0f);
        float y = yb * d * (1.0f / 256.0f);
        // rintf = round-half-even = jnp.round; 15.75 == 63/4 exactly, same
        // single rounding as ((p+2)/4)*63 in the reference.
        float fx_ = rintf((x + 2.0f) * 15.75f);
        float fy_ = rintf((y + 2.0f) * 15.75f);
        float fz_ = rintf((d + 2.0f) * 15.75f);
        ok = ok && (fx_ >= 0.0f) && (fx_ <= 63.0f)
                && (fy_ >= 0.0f) && (fy_ <= 63.0f)
                && (fz_ >= 32.0f) && (fz_ <= 63.0f);
        valid[k] = ok;
        any = any || ok;
        int cx = (int)fx_, cy = (int)fy_, cz = (int)fz_;
        lin[k] = (b << 17) + ((((cx << 6) | cy) << 5) | (cz - 32));
    }

    if (!any) return;

    float4 r4 = ldg_stream(base + 0 * HW + p, pfirst);
    float4 g4 = ldg_stream(base + 1 * HW + p, pfirst);
    float4 b4 = ldg_stream(base + 2 * HW + p, pfirst);
    float rv[4] = {r4.x, r4.y, r4.z, r4.w};
    float gv[4] = {g4.x, g4.y, g4.z, g4.w};
    float bv[4] = {b4.x, b4.y, b4.z, b4.w};

    #pragma unroll
    for (int k = 0; k < 4; k++) {
        if (valid[k]) {
            float* a = (float*)&g_acc[lin[k]];
            asm volatile("red.global.add.v4.f32 [%0], {%1,%2,%3,%4};"
                         :: "l"(a), "f"(1.0f), "f"(rv[k]), "f"(gv[k]),
                            "f"(bv[k]) : "memory");
        }
    }
}

// ------------------------------------------------------------ finalize ----
// Branch-free resolve: count==0 => sums exactly 0 => sum*rcp(max(count,1))==0.
__device__ __forceinline__ void resolve(float4 a, float& occ, float& r,
                                        float& g, float& b) {
    float inv;
    asm("rcp.approx.f32 %0, %1;" : "=f"(inv) : "f"(fmaxf(a.x, 1.0f)));
    occ = (a.x > 0.0f) ? 1.0f : 0.0f;
    r = a.y * inv;
    g = a.z * inv;
    b = a.w * inv;
}

// Thread t owns ONE 128B scratch line (8 entries = czrel chunk [czlo,czlo+8)
// of one (b,cx,cy) row). If the whole chunk lies below mz it is provably
// zero: skip the LDG + discard, emit constant zeros. Otherwise: 4 x LDG.256
// in, 8 x STG.256 out, 1 discard (no writeback).
__global__ __launch_bounds__(256) void finalize_kernel(float* __restrict__ out) {
    int t = blockIdx.x * blockDim.x + threadIdx.x;
    if (t >= NSCRATCH / 8) return;
    uint64_t pfirst = pol_evict_first();

    int s = t << 3;                    // 8 contiguous entries (one 128B line)
    int b = s >> 17;                   // batch
    int sl = s & (SCR_PER_B - 1);      // ((cx*64+cy)*32 + czrel), mult of 8
    int cx = (sl >> 11) & 63;
    int cy = (sl >> 5) & 63;
    int czlo = sl & 31;                // 0, 8, 16, 24

    int rhi = (sl >> 5) << 6;          // (cx*64+cy)*64
    int rocc = rhi + czlo + 32;        // occupied half (32B aligned)
    int rzer = rhi + czlo;             // constant-zero half (32B aligned)
    float* ob = out + (size_t)b * (4 * V3);
    float4 z = make_float4(0.f, 0.f, 0.f, 0.f);

    int mz = row_mz(cx, cy);
    if (czlo + 8 <= mz) {
        // Provably never splatted: pure constant output, zero scratch traffic.
        stg256_hint(ob + rocc,          z, z, pfirst);
        stg256_hint(ob + V3 + rocc,     z, z, pfirst);
        stg256_hint(ob + 2 * V3 + rocc, z, z, pfirst);
        stg256_hint(ob + 3 * V3 + rocc, z, z, pfirst);
        stg256_hint(ob + rzer,          z, z, pfirst);
        stg256_hint(ob + V3 + rzer,     z, z, pfirst);
        stg256_hint(ob + 2 * V3 + rzer, z, z, pfirst);
        stg256_hint(ob + 3 * V3 + rzer, z, z, pfirst);
        return;
    }

    float* sp = (float*)&g_acc[s];
    float4 a[8];
    ldg256(sp,      a[0], a[1]);
    ldg256(sp + 8,  a[2], a[3]);
    ldg256(sp + 16, a[4], a[5]);
    ldg256(sp + 24, a[6], a[7]);

    float4 occ0, rr0, gg0, bb0, occ1, rr1, gg1, bb1;
    resolve(a[0], occ0.x, rr0.x, gg0.x, bb0.x);
    resolve(a[1], occ0.y, rr0.y, gg0.y, bb0.y);
    resolve(a[2], occ0.z, rr0.z, gg0.z, bb0.z);
    resolve(a[3], occ0.w, rr0.w, gg0.w, bb0.w);
    resolve(a[4], occ1.x, rr1.x, gg1.x, bb1.x);
    resolve(a[5], occ1.y, rr1.y, gg1.y, bb1.y);
    resolve(a[6], occ1.z, rr1.z, gg1.z, bb1.z);
    resolve(a[7], occ1.w, rr1.w, gg1.w, bb1.w);

    stg256_hint(ob + rocc,          occ0, occ1, pfirst);
    stg256_hint(ob + V3 + rocc,     rr0,  rr1,  pfirst);
    stg256_hint(ob + 2 * V3 + rocc, gg0,  gg1,  pfirst);
    stg256_hint(ob + 3 * V3 + rocc, bb0,  bb1,  pfirst);

    stg256_hint(ob + rzer,          z, z, pfirst);
    stg256_hint(ob + V3 + rzer,     z, z, pfirst);
    stg256_hint(ob + 2 * V3 + rzer, z, z, pfirst);
    stg256_hint(ob + 3 * V3 + rzer, z, z, pfirst);

    // Drop the dirty scratch line without writeback (DRAM backing stays
    // zero; next call's zero_frustum redirties the reachable tail in L2).
    asm volatile("discard.global.L2 [%0], 128;" :: "l"(&g_acc[s]) : "memory");
}

extern "C" void kernel_launch(void* const* d_in, const int* in_sizes, int n_in,
                              void* d_out, int out_size) {
    const float* rgbd = (const float*)d_in[0];
    float* out = (float*)d_out;

    const int T = 256;
    zero_frustum_kernel<<<(NROWS / 16) * 32 / T, T>>>();   // 1024 CTAs
    splat_kernel<<<(NPIX / 4) / T, T>>>(rgbd);
    finalize_kernel<<<(NSCRATCH / 8) / T, T>>>(out);
}